// round 6
// baseline (speedup 1.0000x reference)
#include <cuda_runtime.h>
#include <cuda_bf16.h>
#include <cstdint>

#define D        512
#define NN       50000
#define NE       200000
#define NG       2048
#define NL       5
#define HID      1024
#define NNP      (NN + 128)            // row-padded for OOB-safe cp.async

// ---------------- scratch (device globals; no allocations allowed) ----------
__device__ float g_h[(size_t)NN * D];
__device__ float g_agg[(size_t)NN * D];
__device__ __nv_bfloat16 g_aghi[(size_t)NNP * D];   // split of agg
__device__ __nv_bfloat16 g_aglo[(size_t)NNP * D];
__device__ __nv_bfloat16 g_xhi[(size_t)NNP * HID];  // split hidden (gemm1 out)
__device__ __nv_bfloat16 g_xlo[(size_t)NNP * HID];
__device__ __nv_bfloat16 g_pshi[(size_t)NG * D];    // split pooled
__device__ __nv_bfloat16 g_pslo[(size_t)NG * D];
__device__ __nv_bfloat16 g_phi[(size_t)NG * D];     // split proj hidden
__device__ __nv_bfloat16 g_plo[(size_t)NG * D];
// transposed + bf16-split weights [N, K]
__device__ __nv_bfloat16 g_w1hi[(size_t)HID * D];
__device__ __nv_bfloat16 g_w1lo[(size_t)HID * D];
__device__ __nv_bfloat16 g_w2hi[(size_t)HID * D];
__device__ __nv_bfloat16 g_w2lo[(size_t)HID * D];

// ================= helpers ==================================================
__device__ __forceinline__ uint32_t s2u(const void* p) {
    uint32_t a;
    asm("{ .reg .u64 t; cvta.to.shared.u64 t, %1; cvt.u32.u64 %0, t; }"
        : "=r"(a) : "l"(p));
    return a;
}
__device__ __forceinline__ void cp16(uint32_t dst, const void* src) {
    asm volatile("cp.async.ca.shared.global [%0], [%1], 16;"
                 :: "r"(dst), "l"(src) : "memory");
}
__device__ __forceinline__ void ldsm4(uint32_t* r, uint32_t a) {
    asm volatile("ldmatrix.sync.aligned.m8n8.x4.shared.b16 {%0,%1,%2,%3}, [%4];"
                 : "=r"(r[0]), "=r"(r[1]), "=r"(r[2]), "=r"(r[3]) : "r"(a));
}
__device__ __forceinline__ void mma_bf16(float* c, const uint32_t* a,
                                         const uint32_t* b) {
    asm volatile(
        "mma.sync.aligned.m16n8k16.row.col.f32.bf16.bf16.f32 "
        "{%0,%1,%2,%3}, {%4,%5,%6,%7}, {%8,%9}, {%0,%1,%2,%3};"
        : "+f"(c[0]), "+f"(c[1]), "+f"(c[2]), "+f"(c[3])
        : "r"(a[0]), "r"(a[1]), "r"(a[2]), "r"(a[3]), "r"(b[0]), "r"(b[1]));
}
__device__ __forceinline__ void redv4(float* p, float x, float y, float z, float w) {
    asm volatile("red.global.add.v4.f32 [%0], {%1,%2,%3,%4};"
                 :: "l"(p), "f"(x), "f"(y), "f"(z), "f"(w) : "memory");
}
__device__ __forceinline__ void split2(float a, float b,
                                       __nv_bfloat162& hi, __nv_bfloat162& lo) {
    hi = __floats2bfloat162_rn(a, b);
    float2 f = __bfloat1622float2(hi);
    lo = __floats2bfloat162_rn(a - f.x, b - f.y);
}

// ================= atom encoder / message passing ===========================
__global__ void k_atom(const int* __restrict__ x,
                       const float* __restrict__ e1,
                       const float* __restrict__ e2) {
    int v = blockIdx.x, t = threadIdx.x;
    int a = x[2 * v], c = x[2 * v + 1];
    float4 u = ((const float4*)(e1 + (size_t)a * D))[t];
    float4 w = ((const float4*)(e2 + (size_t)c * D))[t];
    ((float4*)(g_h + (size_t)v * D))[t] =
        make_float4(u.x + w.x, u.y + w.y, u.z + w.z, u.w + w.w);
}

__global__ void k_init_agg(const float* __restrict__ be1,
                           const float* __restrict__ be2) {
    int v = blockIdx.x, t = threadIdx.x;
    float4 l1 = ((const float4*)(be1 + 6 * D))[t];
    float4 l2 = ((const float4*)(be2 + 3 * D))[t];
    float4 hv = ((const float4*)(g_h + (size_t)v * D))[t];
    ((float4*)(g_agg + (size_t)v * D))[t] =
        make_float4(hv.x + l1.x + l2.x, hv.y + l1.y + l2.y,
                    hv.z + l1.z + l2.z, hv.w + l1.w + l2.w);
}

__global__ void k_scatter(const int* __restrict__ ei,
                          const int* __restrict__ ea,
                          const float* __restrict__ be1,
                          const float* __restrict__ be2) {
    int e = blockIdx.x, t = threadIdx.x;
    int src = ei[e];
    int dst = ei[NE + e];
    int a0 = ea[2 * e], a1 = ea[2 * e + 1];
    float4 hv = ((const float4*)(g_h + (size_t)src * D))[t];
    float4 v1 = ((const float4*)(be1 + (size_t)a0 * D))[t];
    float4 v2 = ((const float4*)(be2 + (size_t)a1 * D))[t];
    float* p = g_agg + (size_t)dst * D + t * 4;
    redv4(p, hv.x + v1.x + v2.x, hv.y + v1.y + v2.y,
             hv.z + v1.z + v2.z, hv.w + v1.w + v2.w);
}

// ================= elementwise fp32 -> bf16 hi/lo split =====================
__global__ void k_splitA(const float* __restrict__ in,
                         __nv_bfloat16* __restrict__ hi,
                         __nv_bfloat16* __restrict__ lo, int n) {
    int i = (blockIdx.x * 256 + threadIdx.x) * 4;
    if (i >= n) return;
    float4 v = *(const float4*)(in + i);
    __nv_bfloat162 h0, l0, h1, l1;
    split2(v.x, v.y, h0, l0);
    split2(v.z, v.w, h1, l1);
    *(__nv_bfloat162*)(hi + i)     = h0;
    *(__nv_bfloat162*)(hi + i + 2) = h1;
    *(__nv_bfloat162*)(lo + i)     = l0;
    *(__nv_bfloat162*)(lo + i + 2) = l1;
}

// ================= weight transpose + bf16 split ============================
__global__ void k_prepW(const float* __restrict__ W, int K, int N,
                        __nv_bfloat16* __restrict__ whi,
                        __nv_bfloat16* __restrict__ wlo) {
    __shared__ float t[32][33];
    int n0 = blockIdx.x * 32, k0 = blockIdx.y * 32;
    int tx = threadIdx.x, ty = threadIdx.y;   // 32 x 8
#pragma unroll
    for (int i = 0; i < 4; i++)
        t[ty + i * 8][tx] = W[(size_t)(k0 + ty + i * 8) * N + n0 + tx];
    __syncthreads();
#pragma unroll
    for (int i = 0; i < 4; i++) {
        int n = n0 + ty + i * 8, k = k0 + tx;
        float v = t[tx][ty + i * 8];
        __nv_bfloat16 h = __float2bfloat16_rn(v);
        whi[(size_t)n * K + k] = h;
        wlo[(size_t)n * K + k] = __float2bfloat16_rn(v - __bfloat162float(h));
    }
}

// ================= bf16-split mma.sync GEMM (all-cp.async) ==================
// C[M,N] = epi(A @ W + bias); A split in Ahi/Alo [M,K] bf16 row-major,
// W split transposed in Bhi/Blo [N,K] bf16. CTA tile 128x128, BK=32,
// 128 threads (4 warps of 64x64), double-buffered cp.async, ldmatrix.
// OM: 0 = f32 out, 1 = f32+relu out, 2 = bf16-split+relu out.
#define KP    40
#define MAT_E (128 * KP)
#define STAGE_E (4 * MAT_E)            // Ahi, Alo, Bhi, Blo
#define SMEM_G  (2 * STAGE_E * 2)      // 81920 bytes

template <int OM>
__global__ void __launch_bounds__(128, 2)
k_gemm(const __nv_bfloat16* __restrict__ Ahi,
       const __nv_bfloat16* __restrict__ Alo,
       const __nv_bfloat16* __restrict__ Bhi,
       const __nv_bfloat16* __restrict__ Blo,
       const float* __restrict__ bias,
       float* __restrict__ C,
       __nv_bfloat16* __restrict__ Chi,
       __nv_bfloat16* __restrict__ Clo,
       int M, int N, int K) {
    extern __shared__ __align__(16) __nv_bfloat16 sm[];
    const int tid = threadIdx.x;
    const int lane = tid & 31;
    const int wid = tid >> 5;
    const int g = lane >> 2, tg = lane & 3;
    const int wm = (wid >> 1) * 64, wn = (wid & 1) * 64;
    const int n0 = blockIdx.x * 128, m0 = blockIdx.y * 128;  // x = n (L2 reuse of A)
    const int NC = K >> 5;

    const uint32_t sbase = s2u(sm);

    const int lA_row = lane & 15;
    const int lA_k   = (lane >> 4) << 3;
    const int lB_n   = ((lane >> 4) << 3) + (lane & 7);
    const int lB_k   = ((lane >> 3) & 1) << 3;

    float acc[4][8][4];
#pragma unroll
    for (int i = 0; i < 4; i++)
#pragma unroll
        for (int j = 0; j < 8; j++)
#pragma unroll
            for (int k = 0; k < 4; k++) acc[i][j][k] = 0.f;

    // per-thread cp.async coords: 4 iters/matrix, r = idx>>2, c4 = idx&3
    auto cpChunk = [&](int c, int st) {
        uint32_t sA = sbase + (st * STAGE_E) * 2;
        uint32_t sAl = sA + MAT_E * 2;
        uint32_t sB = sA + 2 * MAT_E * 2;
        uint32_t sBl = sA + 3 * MAT_E * 2;
        const __nv_bfloat16* ah = Ahi + (size_t)m0 * K + c * 32;
        const __nv_bfloat16* al = Alo + (size_t)m0 * K + c * 32;
        const __nv_bfloat16* bh = Bhi + (size_t)n0 * K + c * 32;
        const __nv_bfloat16* bl = Blo + (size_t)n0 * K + c * 32;
#pragma unroll
        for (int i = 0; i < 4; i++) {
            int idx = tid + i * 128;
            int r = idx >> 2, c4 = idx & 3;
            uint32_t so = (uint32_t)(r * KP + c4 * 8) * 2;
            size_t go = (size_t)r * K + c4 * 8;
            cp16(sA + so, ah + go);
            cp16(sAl + so, al + go);
            cp16(sB + so, bh + go);
            cp16(sBl + so, bl + go);
        }
    };

    cpChunk(0, 0);
    asm volatile("cp.async.commit_group;" ::: "memory");

    for (int c = 0; c < NC; c++) {
        const int cur = c & 1;
        if (c + 1 < NC) {
            cpChunk(c + 1, (c + 1) & 1);
            asm volatile("cp.async.commit_group;" ::: "memory");
            asm volatile("cp.async.wait_group 1;" ::: "memory");
        } else {
            asm volatile("cp.async.wait_group 0;" ::: "memory");
        }
        __syncthreads();

        const uint32_t ahB = sbase + (cur * STAGE_E) * 2;
        const uint32_t alB = ahB + MAT_E * 2;
        const uint32_t bhB = ahB + 2 * MAT_E * 2;
        const uint32_t blB = ahB + 3 * MAT_E * 2;

#pragma unroll
        for (int ks = 0; ks < 32; ks += 16) {
            uint32_t bh[8][2], bl[8][2];
#pragma unroll
            for (int np = 0; np < 4; np++) {
                uint32_t o = (uint32_t)(((wn + np * 16 + lB_n) * KP + ks + lB_k) * 2);
                uint32_t r[4];
                ldsm4(r, bhB + o);
                bh[np * 2][0] = r[0]; bh[np * 2][1] = r[1];
                bh[np * 2 + 1][0] = r[2]; bh[np * 2 + 1][1] = r[3];
                ldsm4(r, blB + o);
                bl[np * 2][0] = r[0]; bl[np * 2][1] = r[1];
                bl[np * 2 + 1][0] = r[2]; bl[np * 2 + 1][1] = r[3];
            }
#pragma unroll
            for (int mt = 0; mt < 4; mt++) {
                uint32_t o = (uint32_t)(((wm + mt * 16 + lA_row) * KP + ks + lA_k) * 2);
                uint32_t ah[4], al[4];
                ldsm4(ah, ahB + o);
                ldsm4(al, alB + o);
#pragma unroll
                for (int nt = 0; nt < 8; nt++) {
                    mma_bf16(acc[mt][nt], ah, bh[nt]);
                    mma_bf16(acc[mt][nt], ah, bl[nt]);
                    mma_bf16(acc[mt][nt], al, bh[nt]);
                }
            }
        }
        __syncthreads();  // all reads of 'cur' done before it is refilled
    }

    // ---- epilogue ----------------------------------------------------------
#pragma unroll
    for (int mt = 0; mt < 4; mt++) {
        int r0 = m0 + wm + mt * 16 + g;
        int r1 = r0 + 8;
#pragma unroll
        for (int nt = 0; nt < 8; nt++) {
            int n = n0 + wn + nt * 8 + tg * 2;
            float2 bi = *(const float2*)(bias + n);
            float2 v0 = make_float2(acc[mt][nt][0] + bi.x, acc[mt][nt][1] + bi.y);
            float2 v1 = make_float2(acc[mt][nt][2] + bi.x, acc[mt][nt][3] + bi.y);
            if (OM >= 1) {
                v0.x = fmaxf(v0.x, 0.f); v0.y = fmaxf(v0.y, 0.f);
                v1.x = fmaxf(v1.x, 0.f); v1.y = fmaxf(v1.y, 0.f);
            }
            if (OM == 2) {
                __nv_bfloat162 h, l;
                if (r0 < M) {
                    split2(v0.x, v0.y, h, l);
                    *(__nv_bfloat162*)(Chi + (size_t)r0 * N + n) = h;
                    *(__nv_bfloat162*)(Clo + (size_t)r0 * N + n) = l;
                }
                if (r1 < M) {
                    split2(v1.x, v1.y, h, l);
                    *(__nv_bfloat162*)(Chi + (size_t)r1 * N + n) = h;
                    *(__nv_bfloat162*)(Clo + (size_t)r1 * N + n) = l;
                }
            } else {
                if (r0 < M) *(float2*)(C + (size_t)r0 * N + n) = v0;
                if (r1 < M) *(float2*)(C + (size_t)r1 * N + n) = v1;
            }
        }
    }
}

// ================= mean pooling -> split bf16 (batch sorted) ================
__global__ void k_pool(const int* __restrict__ batch) {
    int g = blockIdx.x, t = threadIdx.x;
    int lo = 0, hi = NN;
    while (lo < hi) { int mid = (lo + hi) >> 1; if (batch[mid] < g) lo = mid + 1; else hi = mid; }
    int s = lo;
    hi = NN;
    while (lo < hi) { int mid = (lo + hi) >> 1; if (batch[mid] < g + 1) lo = mid + 1; else hi = mid; }
    int e = lo;
    float4 sum = make_float4(0.f, 0.f, 0.f, 0.f);
    for (int v = s; v < e; v++) {
        float4 hv = ((const float4*)(g_h + (size_t)v * D))[t];
        sum.x += hv.x; sum.y += hv.y; sum.z += hv.z; sum.w += hv.w;
    }
    float inv = (e > s) ? 1.0f / (float)(e - s) : 0.0f;
    float4 m = make_float4(sum.x * inv, sum.y * inv, sum.z * inv, sum.w * inv);
    __nv_bfloat162 h0, l0, h1, l1;
    split2(m.x, m.y, h0, l0);
    split2(m.z, m.w, h1, l1);
    size_t o = (size_t)g * D + t * 4;
    *(__nv_bfloat162*)(g_pshi + o)     = h0;
    *(__nv_bfloat162*)(g_pshi + o + 2) = h1;
    *(__nv_bfloat162*)(g_pslo + o)     = l0;
    *(__nv_bfloat162*)(g_pslo + o + 2) = l1;
}

// ================= launch ===================================================
extern "C" void kernel_launch(void* const* d_in, const int* in_sizes, int n_in,
                              void* d_out, int out_size) {
    const int*   x   = (const int*)d_in[0];
    const int*   ei  = (const int*)d_in[1];
    const int*   ea  = (const int*)d_in[2];
    const int*   bat = (const int*)d_in[3];
    const float* ae1 = (const float*)d_in[4];
    const float* ae2 = (const float*)d_in[5];
    const float* be1 = (const float*)d_in[6];
    const float* be2 = (const float*)d_in[7];
    const float* W1  = (const float*)d_in[8];
    const float* b1  = (const float*)d_in[9];
    const float* W2  = (const float*)d_in[10];
    const float* b2  = (const float*)d_in[11];
    const float* pW1 = (const float*)d_in[12];
    const float* pb1 = (const float*)d_in[13];
    const float* pW2 = (const float*)d_in[14];
    const float* pb2 = (const float*)d_in[15];
    float* out = (float*)d_out;

    cudaFuncSetAttribute(k_gemm<0>, cudaFuncAttributeMaxDynamicSharedMemorySize, SMEM_G);
    cudaFuncSetAttribute(k_gemm<1>, cudaFuncAttributeMaxDynamicSharedMemorySize, SMEM_G);
    cudaFuncSetAttribute(k_gemm<2>, cudaFuncAttributeMaxDynamicSharedMemorySize, SMEM_G);

    float *p_h, *p_agg;
    __nv_bfloat16 *p_aghi, *p_aglo, *p_xhi, *p_xlo, *p_pshi, *p_pslo,
                  *p_phi, *p_plo, *p_w1hi, *p_w1lo, *p_w2hi, *p_w2lo;
    cudaGetSymbolAddress((void**)&p_h, g_h);
    cudaGetSymbolAddress((void**)&p_agg, g_agg);
    cudaGetSymbolAddress((void**)&p_aghi, g_aghi);
    cudaGetSymbolAddress((void**)&p_aglo, g_aglo);
    cudaGetSymbolAddress((void**)&p_xhi, g_xhi);
    cudaGetSymbolAddress((void**)&p_xlo, g_xlo);
    cudaGetSymbolAddress((void**)&p_pshi, g_pshi);
    cudaGetSymbolAddress((void**)&p_pslo, g_pslo);
    cudaGetSymbolAddress((void**)&p_phi, g_phi);
    cudaGetSymbolAddress((void**)&p_plo, g_plo);
    cudaGetSymbolAddress((void**)&p_w1hi, g_w1hi);
    cudaGetSymbolAddress((void**)&p_w1lo, g_w1lo);
    cudaGetSymbolAddress((void**)&p_w2hi, g_w2hi);
    cudaGetSymbolAddress((void**)&p_w2lo, g_w2lo);

    k_atom<<<NN, 128>>>(x, ae1, ae2);

    const int MT = (NN + 127) / 128;
    for (int l = 0; l < NL; l++) {
        const float* bl1 = be1 + (size_t)l * 8 * D;
        const float* bl2 = be2 + (size_t)l * 4 * D;
        k_init_agg<<<NN, 128>>>(bl1, bl2);
        k_scatter<<<NE, 128>>>(ei, ea, bl1, bl2);
        k_prepW<<<dim3(HID / 32, D / 32), dim3(32, 8)>>>(
            W1 + (size_t)l * D * HID, D, HID, p_w1hi, p_w1lo);
        k_prepW<<<dim3(D / 32, HID / 32), dim3(32, 8)>>>(
            W2 + (size_t)l * HID * D, HID, D, p_w2hi, p_w2lo);
        k_splitA<<<(NN * D + 1023) / 1024, 256>>>(p_agg, p_aghi, p_aglo, NN * D);

        // hidden(split) = relu(agg @ W1 + b1)
        k_gemm<2><<<dim3(HID / 128, MT), 128, SMEM_G>>>(
            p_aghi, p_aglo, p_w1hi, p_w1lo, b1 + (size_t)l * HID,
            nullptr, p_xhi, p_xlo, NN, HID, D);
        // h = hidden @ W2 + b2  (+relu except last layer)
        if (l < NL - 1)
            k_gemm<1><<<dim3(D / 128, MT), 128, SMEM_G>>>(
                p_xhi, p_xlo, p_w2hi, p_w2lo, b2 + (size_t)l * D,
                p_h, nullptr, nullptr, NN, D, HID);
        else
            k_gemm<0><<<dim3(D / 128, MT), 128, SMEM_G>>>(
                p_xhi, p_xlo, p_w2hi, p_w2lo, b2 + (size_t)l * D,
                p_h, nullptr, nullptr, NN, D, HID);
    }

    k_pool<<<NG, 128>>>(bat);

    // projection head
    k_prepW<<<dim3(D / 32, D / 32), dim3(32, 8)>>>(pW1, D, D, p_w1hi, p_w1lo);
    k_gemm<2><<<dim3(D / 128, NG / 128), 128, SMEM_G>>>(
        p_pshi, p_pslo, p_w1hi, p_w1lo, pb1, nullptr, p_phi, p_plo, NG, D, D);
    k_prepW<<<dim3(D / 32, D / 32), dim3(32, 8)>>>(pW2, D, D, p_w2hi, p_w2lo);
    k_gemm<0><<<dim3(D / 128, NG / 128), 128, SMEM_G>>>(
        p_phi, p_plo, p_w2hi, p_w2lo, pb2, out, nullptr, nullptr, NG, D, D);
}